// round 4
// baseline (speedup 1.0000x reference)
#include <cuda_runtime.h>
#include <cstdint>

// Problem constants (IN_SHAPE = (32,3,512,512), OUT_HW = 256)
#define N_PLANES   (32 * 3)      // N*C
#define IN_HW      512
#define OUT_HW     256
#define SCRATCH_ELEMS ((size_t)N_PLANES * IN_HW * OUT_HW)   // 32*3*512*256 = 12,582,912

// Scratch for the intermediate (W-resized) tensor: (N,C,512,256) fp32 = ~50 MB.
// Static __device__ array — no runtime allocation (harness rule).
__device__ float g_scratch[N_PLANES * IN_HW * OUT_HW];

// ---------------------------------------------------------------------------
// Pass 1: resize along W (last dim). One CTA per input row (N*C*512 = 49152 rows).
// Row (512 floats = 2 KB) is cooperatively loaded into smem once -> each input
// element hits DRAM exactly once. Each thread produces one output column via
// taps smem gathers. w/fov loads hit L1/L2 (same addresses every block).
// ---------------------------------------------------------------------------
__global__ void __launch_bounds__(OUT_HW)
hpass_kernel(const float* __restrict__ in,
             const float* __restrict__ w,
             const int*   __restrict__ fov,
             float*       __restrict__ out1,
             int taps)
{
    __shared__ float row[IN_HW];
    const int r = blockIdx.x;          // combined (n,c,h) row index
    const int t = threadIdx.x;         // output column 0..255

    // cooperative row load: 256 threads x float2 = 512 floats
    const float2* src2 = reinterpret_cast<const float2*>(in + (size_t)r * IN_HW);
    reinterpret_cast<float2*>(row)[t] = src2[t];
    __syncthreads();

    float sum = 0.0f;
    if (taps == 8) {
#pragma unroll
        for (int j = 0; j < 8; ++j) {
            const int i = j * OUT_HW + t;
            sum = fmaf(__ldg(w + i), row[__ldg(fov + i)], sum);
        }
    } else {
        for (int j = 0; j < taps; ++j) {
            const int i = j * OUT_HW + t;
            sum = fmaf(__ldg(w + i), row[__ldg(fov + i)], sum);
        }
    }
    out1[(size_t)r * OUT_HW + t] = sum;
}

// ---------------------------------------------------------------------------
// Pass 2: resize along H. One thread per float4 of the output.
// All threads in a warp share the same oh -> w/fov loads are uniform
// broadcasts; scratch reads are contiguous 128B per warp per tap.
// ---------------------------------------------------------------------------
__global__ void __launch_bounds__(256)
vpass_kernel(const float* __restrict__ s,
             const float* __restrict__ w,
             const int*   __restrict__ fov,
             float4*      __restrict__ out,
             int taps)
{
    const int idx = blockIdx.x * blockDim.x + threadIdx.x;  // over out_elems/4
    const int ow4 = idx & 63;               // float4 column 0..63
    const int oh  = (idx >> 6) & (OUT_HW - 1);
    const int pl  = idx >> 14;              // plane 0..95 (256*64 = 2^14 float4 per plane)

    const float4* base =
        reinterpret_cast<const float4*>(s + (size_t)pl * IN_HW * OUT_HW) + ow4;

    float4 acc = make_float4(0.f, 0.f, 0.f, 0.f);
    if (taps == 8) {
#pragma unroll
        for (int j = 0; j < 8; ++j) {
            const int i  = j * OUT_HW + oh;
            const float wj = __ldg(w + i);
            const float4 v = base[(size_t)__ldg(fov + i) * (OUT_HW / 4)];
            acc.x = fmaf(wj, v.x, acc.x);
            acc.y = fmaf(wj, v.y, acc.y);
            acc.z = fmaf(wj, v.z, acc.z);
            acc.w = fmaf(wj, v.w, acc.w);
        }
    } else {
        for (int j = 0; j < taps; ++j) {
            const int i  = j * OUT_HW + oh;
            const float wj = __ldg(w + i);
            const float4 v = base[(size_t)__ldg(fov + i) * (OUT_HW / 4)];
            acc.x = fmaf(wj, v.x, acc.x);
            acc.y = fmaf(wj, v.y, acc.y);
            acc.z = fmaf(wj, v.z, acc.z);
            acc.w = fmaf(wj, v.w, acc.w);
        }
    }
    out[idx] = acc;
}

// ---------------------------------------------------------------------------
// Inputs (metadata order): in_tensor f32, w2 f32, fov2 i32, w3 f32, fov3 i32.
// Reference applies H (dim 2, tables w2/fov2) then W (dim 3, tables w3/fov3);
// separable => we do W first (w3/fov3) into scratch, then H (w2/fov2).
// ---------------------------------------------------------------------------
extern "C" void kernel_launch(void* const* d_in, const int* in_sizes, int n_in,
                              void* d_out, int out_size)
{
    const float* in   = (const float*)d_in[0];
    const float* w2   = (const float*)d_in[1];
    const int*   fov2 = (const int*)  d_in[2];
    const float* w3   = (const float*)d_in[3];
    const int*   fov3 = (const int*)  d_in[4];

    const int taps = in_sizes[2] / OUT_HW;   // fov2 has taps*256 elements

    float* scratch = nullptr;
    cudaGetSymbolAddress((void**)&scratch, g_scratch);

    // Pass 1 (W resize): (N*C*512) rows -> scratch (N,C,512,256)
    const int n_rows = N_PLANES * IN_HW;     // 49152
    hpass_kernel<<<n_rows, OUT_HW>>>(in, w3, fov3, scratch, taps);

    // Pass 2 (H resize): scratch -> out (N,C,256,256), float4-vectorized
    const int out_elems = N_PLANES * OUT_HW * OUT_HW;   // 6,291,456
    const int n_vec4    = out_elems / 4;                // 1,572,864
    vpass_kernel<<<n_vec4 / 256, 256>>>(scratch, w2, fov2, (float4*)d_out, taps);
}

// round 6
// speedup vs baseline: 1.0920x; 1.0920x over previous
#include <cuda_runtime.h>
#include <cstdint>

// Problem constants (IN_SHAPE = (32,3,512,512), OUT_HW = 256, scale 0.5)
#define N_PLANES   96          // N*C
#define IN_HW      512
#define OUT_HW     256
#define R_BLK      32          // output rows per CTA (fused path)
#define OH_BLKS    (OUT_HW / R_BLK)          // 8
#define MAX_ROWS   72          // max input-row span per block (<= 2*R_BLK+8)
#define TAPS       8

// Scratch for the generic two-pass fallback only (~50 MB, static => legal).
__device__ float g_scratch[(size_t)N_PLANES * IN_HW * OUT_HW];

// ===========================================================================
// FUSED kernel (taps == 8). One CTA per (plane, 32-row output block).
// smem layout (dynamic): inter[MAX_ROWS][256] then rowbuf[8][512].
// ===========================================================================
__global__ void __launch_bounds__(256, 2)
fused_resize_kernel(const float* __restrict__ in,
                    const float* __restrict__ w2, const int* __restrict__ fov2,
                    const float* __restrict__ w3, const int* __restrict__ fov3,
                    float* __restrict__ out)
{
    extern __shared__ float smem[];
    float* inter  = smem;                         // MAX_ROWS * 256
    float* rowbuf = smem + MAX_ROWS * OUT_HW;     // 8 * 512
    __shared__ int s_rmin, s_rmax;

    const int t    = threadIdx.x;
    const int lane = t & 31;
    const int wid  = t >> 5;
    const int plane = blockIdx.x >> 3;            // 0..95
    const int oh0   = (blockIdx.x & (OH_BLKS - 1)) * R_BLK;

    // ---- input-row span: min/max of fov2 over (8 taps x 32 oh) -------------
    // thread t reads fov2[wid*256 + oh0 + lane]  (wid = tap j, lane = oh off)
    int v = __ldg(fov2 + wid * OUT_HW + oh0 + lane);
    int vmin = v, vmax = v;
#pragma unroll
    for (int s = 16; s; s >>= 1) {
        vmin = min(vmin, __shfl_xor_sync(0xffffffffu, vmin, s));
        vmax = max(vmax, __shfl_xor_sync(0xffffffffu, vmax, s));
    }
    if (t == 0) { s_rmin = 1 << 30; s_rmax = -1; }
    __syncthreads();
    if (lane == 0) { atomicMin(&s_rmin, vmin); atomicMax(&s_rmax, vmax); }
    __syncthreads();
    const int rmin  = s_rmin;
    const int nrows = min(s_rmax - rmin + 1, MAX_ROWS);

    // ---- W-pass: each warp streams rows rmin+wid, +8, ... ------------------
    // Load 512 floats (4x LDG.128/lane, prefetched one row ahead), stage in
    // per-warp smem, gather 8 taps per output column (stride-32 lane->ow map
    // keeps gather conflicts at 2-way), write intermediate row.
    {
        float* rb = rowbuf + wid * IN_HW;
        const float4* plane_in =
            reinterpret_cast<const float4*>(in + (size_t)plane * IN_HW * IN_HW);

        int rl = wid;
        float4 a0, a1, a2, a3;
        if (rl < nrows) {
            const float4* src = plane_in + (size_t)(rmin + rl) * (IN_HW / 4);
            a0 = src[lane]; a1 = src[lane + 32]; a2 = src[lane + 64]; a3 = src[lane + 96];
        }
        for (; rl < nrows; rl += 8) {
            float4* rb4 = reinterpret_cast<float4*>(rb);
            rb4[lane] = a0; rb4[lane + 32] = a1; rb4[lane + 64] = a2; rb4[lane + 96] = a3;
            __syncwarp();

            // prefetch next row while gathers run
            if (rl + 8 < nrows) {
                const float4* src = plane_in + (size_t)(rmin + rl + 8) * (IN_HW / 4);
                a0 = src[lane]; a1 = src[lane + 32]; a2 = src[lane + 64]; a3 = src[lane + 96];
            }

            float* dst = inter + rl * OUT_HW;
#pragma unroll
            for (int k = 0; k < 8; ++k) {
                const int ow = lane + 32 * k;
                float s = 0.0f;
#pragma unroll
                for (int j = 0; j < TAPS; ++j) {
                    const int i = j * OUT_HW + ow;
                    s = fmaf(__ldg(w3 + i), rb[__ldg(fov3 + i)], s);
                }
                dst[ow] = s;
            }
            __syncwarp();   // all gathers done before rowbuf is overwritten
        }
    }
    __syncthreads();

    // ---- H-pass: 32x256 outputs, float4-vectorized -------------------------
    // idx = q*256 + t : ow4 = idx&63 (lane-consecutive -> conflict-free LDS.128,
    // coalesced STG.128), ohl = idx>>6 (warp-uniform -> broadcast table loads).
    {
        const float4* interv = reinterpret_cast<const float4*>(inter);
        float4* outv = reinterpret_cast<float4*>(out + (size_t)plane * OUT_HW * OUT_HW);
#pragma unroll
        for (int q = 0; q < 8; ++q) {
            const int idx = q * 256 + t;
            const int ow4 = idx & 63;
            const int oh  = oh0 + (idx >> 6);
            float4 acc = make_float4(0.f, 0.f, 0.f, 0.f);
#pragma unroll
            for (int j = 0; j < TAPS; ++j) {
                const int i   = j * OUT_HW + oh;
                const float wj = __ldg(w2 + i);
                const int r    = __ldg(fov2 + i) - rmin;
                const float4 x = interv[r * (OUT_HW / 4) + ow4];
                acc.x = fmaf(wj, x.x, acc.x);
                acc.y = fmaf(wj, x.y, acc.y);
                acc.z = fmaf(wj, x.z, acc.z);
                acc.w = fmaf(wj, x.w, acc.w);
            }
            outv[oh * (OUT_HW / 4) + ow4] = acc;
        }
    }
}

// ===========================================================================
// Generic two-pass fallback (any taps) — previous passing implementation.
// ===========================================================================
__global__ void __launch_bounds__(OUT_HW)
hpass_kernel(const float* __restrict__ in, const float* __restrict__ w,
             const int* __restrict__ fov, float* __restrict__ out1, int taps)
{
    __shared__ float row[IN_HW];
    const int r = blockIdx.x;
    const int t = threadIdx.x;
    const float2* src2 = reinterpret_cast<const float2*>(in + (size_t)r * IN_HW);
    reinterpret_cast<float2*>(row)[t] = src2[t];
    __syncthreads();
    float sum = 0.0f;
    for (int j = 0; j < taps; ++j) {
        const int i = j * OUT_HW + t;
        sum = fmaf(__ldg(w + i), row[__ldg(fov + i)], sum);
    }
    out1[(size_t)r * OUT_HW + t] = sum;
}

__global__ void __launch_bounds__(256)
vpass_kernel(const float* __restrict__ s, const float* __restrict__ w,
             const int* __restrict__ fov, float4* __restrict__ out, int taps)
{
    const int idx = blockIdx.x * blockDim.x + threadIdx.x;
    const int ow4 = idx & 63;
    const int oh  = (idx >> 6) & (OUT_HW - 1);
    const int pl  = idx >> 14;
    const float4* base =
        reinterpret_cast<const float4*>(s + (size_t)pl * IN_HW * OUT_HW) + ow4;
    float4 acc = make_float4(0.f, 0.f, 0.f, 0.f);
    for (int j = 0; j < taps; ++j) {
        const int i = j * OUT_HW + oh;
        const float wj = __ldg(w + i);
        const float4 v = base[(size_t)__ldg(fov + i) * (OUT_HW / 4)];
        acc.x = fmaf(wj, v.x, acc.x);
        acc.y = fmaf(wj, v.y, acc.y);
        acc.z = fmaf(wj, v.z, acc.z);
        acc.w = fmaf(wj, v.w, acc.w);
    }
    out[idx] = acc;
}

// ===========================================================================
// Inputs (metadata order): in_tensor f32, w2 f32, fov2 i32, w3 f32, fov3 i32.
// ===========================================================================
extern "C" void kernel_launch(void* const* d_in, const int* in_sizes, int n_in,
                              void* d_out, int out_size)
{
    const float* in   = (const float*)d_in[0];
    const float* w2   = (const float*)d_in[1];
    const int*   fov2 = (const int*)  d_in[2];
    const float* w3   = (const float*)d_in[3];
    const int*   fov3 = (const int*)  d_in[4];

    const int taps = in_sizes[2] / OUT_HW;

    if (taps == TAPS) {
        const int smem_bytes = (MAX_ROWS * OUT_HW + 8 * IN_HW) * (int)sizeof(float); // 90112
        cudaFuncSetAttribute(fused_resize_kernel,
                             cudaFuncAttributeMaxDynamicSharedMemorySize, smem_bytes);
        fused_resize_kernel<<<N_PLANES * OH_BLKS, 256, smem_bytes>>>(
            in, w2, fov2, w3, fov3, (float*)d_out);
    } else {
        float* scratch = nullptr;
        cudaGetSymbolAddress((void**)&scratch, g_scratch);
        hpass_kernel<<<N_PLANES * IN_HW, OUT_HW>>>(in, w3, fov3, scratch, taps);
        const int n_vec4 = N_PLANES * OUT_HW * OUT_HW / 4;
        vpass_kernel<<<n_vec4 / 256, 256>>>(scratch, w2, fov2, (float4*)d_out, taps);
    }
}

// round 7
// speedup vs baseline: 1.3712x; 1.2556x over previous
#include <cuda_runtime.h>
#include <cstdint>

// Problem constants (IN_SHAPE = (32,3,512,512), OUT_HW = 256, scale 0.5)
#define N_PLANES   96          // N*C
#define IN_HW      512
#define OUT_HW     256
#define R_BLK      16          // output rows per CTA (fused path)
#define OH_BLKS    (OUT_HW / R_BLK)          // 16
#define MAX_ROWS_F 40          // max input-row span for R_BLK=16 (38 + margin)
#define TAPS       8
#define SMEM_FLOATS (MAX_ROWS_F * IN_HW)     // 20480 floats = 80 KB

// Scratch for the generic two-pass fallback only (~50 MB, static => legal).
__device__ float g_scratch[(size_t)N_PLANES * IN_HW * OUT_HW];

// ===========================================================================
// FUSED kernel (taps == 8). One CTA per (plane, 16-row output block).
// smem: MAX_ROWS_F rows of 512 floats, DEINTERLEAVED per row:
//   even input elements at [0,256), odd at [256,512).
// The stride-2 W gather (idx = 2*ow-5+j interior) then maps consecutive lanes
// to consecutive smem addresses -> conflict-free LDS.
// inter[r] (256 floats) is written IN PLACE over row r's front half after all
// threads finish gathering row r (one __syncthreads per row).
// ===========================================================================
__global__ void __launch_bounds__(256, 2)
fused_resize_kernel(const float* __restrict__ in,
                    const float* __restrict__ w2, const int* __restrict__ fov2,
                    const float* __restrict__ w3, const int* __restrict__ fov3,
                    float* __restrict__ out)
{
    extern __shared__ float smf[];
    __shared__ int s_rmin, s_rmax;

    const int t     = threadIdx.x;
    const int plane = blockIdx.x >> 4;                 // / OH_BLKS
    const int oh0   = (blockIdx.x & (OH_BLKS - 1)) * R_BLK;

    // ---- input-row span: min/max of fov2 over (8 taps x 16 oh) -------------
    {
        const int idx = t & 127;
        const int tap = idx >> 4, oo = idx & 15;
        int v = __ldg(fov2 + tap * OUT_HW + oh0 + oo);
        int vmin = v, vmax = v;
#pragma unroll
        for (int s = 16; s; s >>= 1) {
            vmin = min(vmin, __shfl_xor_sync(0xffffffffu, vmin, s));
            vmax = max(vmax, __shfl_xor_sync(0xffffffffu, vmax, s));
        }
        if (t == 0) { s_rmin = 1 << 30; s_rmax = -1; }
        __syncthreads();
        if ((t & 31) == 0) { atomicMin(&s_rmin, vmin); atomicMax(&s_rmax, vmax); }
        __syncthreads();
    }
    const int rmin  = s_rmin;
    const int nrows = min(s_rmax - rmin + 1, MAX_ROWS_F);

    // ---- per-thread W tables, loaded ONCE (ow = t) -------------------------
    float wreg[TAPS];
    int   preg[TAPS];           // deinterleaved smem position within a row
#pragma unroll
    for (int j = 0; j < TAPS; ++j) {
        wreg[j] = __ldg(w3 + j * OUT_HW + t);
        const int idx = __ldg(fov3 + j * OUT_HW + t);
        preg[j] = (idx >> 1) + ((idx & 1) << 8);
    }

    // ---- load nrows input rows, deinterleaving on the fly ------------------
    {
        const float4* pin = reinterpret_cast<const float4*>(
                                in + (size_t)plane * IN_HW * IN_HW)
                            + (size_t)rmin * (IN_HW / 4);
        float2* sm2 = reinterpret_cast<float2*>(smf);
        const int total = nrows * (IN_HW / 4);
        for (int i = t; i < total; i += 256) {
            const int row = i >> 7, c4 = i & 127;
            const float4 g = pin[(size_t)row * (IN_HW / 4) + c4];
            sm2[row * 256 + c4]       = make_float2(g.x, g.z);   // even phase
            sm2[row * 256 + 128 + c4] = make_float2(g.y, g.w);   // odd phase
        }
    }
    __syncthreads();

    // ---- W-pass: lockstep per row, conflict-free gathers, in-place inter ---
    for (int r = 0; r < nrows; ++r) {
        const float* rb = smf + r * IN_HW;
        float s0 = 0.0f, s1 = 0.0f;                 // 2 accums -> shorter chain
#pragma unroll
        for (int j = 0; j < TAPS; j += 2) {
            s0 = fmaf(wreg[j],     rb[preg[j]],     s0);
            s1 = fmaf(wreg[j + 1], rb[preg[j + 1]], s1);
        }
        __syncthreads();                            // all gathers of row r done
        smf[r * IN_HW + t] = s0 + s1;               // inter[r][t]
    }
    __syncthreads();

    // ---- H-pass: 16x256 outputs, float4-vectorized -------------------------
    const float4* iv = reinterpret_cast<const float4*>(smf);  // inter[r] @ r*128
    float4* ov = reinterpret_cast<float4*>(out + (size_t)plane * OUT_HW * OUT_HW);
#pragma unroll
    for (int q = 0; q < 4; ++q) {
        const int idx = q * 256 + t;
        const int ow4 = idx & 63;                   // lane-consecutive
        const int oh  = oh0 + (idx >> 6);           // warp-uniform
        float4 acc = make_float4(0.f, 0.f, 0.f, 0.f);
#pragma unroll
        for (int j = 0; j < TAPS; ++j) {
            const int i    = j * OUT_HW + oh;
            const float wj = __ldg(w2 + i);
            const int r    = min(__ldg(fov2 + i) - rmin, MAX_ROWS_F - 1);
            const float4 x = iv[r * (IN_HW / 4) + ow4];
            acc.x = fmaf(wj, x.x, acc.x);
            acc.y = fmaf(wj, x.y, acc.y);
            acc.z = fmaf(wj, x.z, acc.z);
            acc.w = fmaf(wj, x.w, acc.w);
        }
        ov[oh * (OUT_HW / 4) + ow4] = acc;
    }
}

// ===========================================================================
// Generic two-pass fallback (any taps).
// ===========================================================================
__global__ void __launch_bounds__(OUT_HW)
hpass_kernel(const float* __restrict__ in, const float* __restrict__ w,
             const int* __restrict__ fov, float* __restrict__ out1, int taps)
{
    __shared__ float row[IN_HW];
    const int r = blockIdx.x;
    const int t = threadIdx.x;
    const float2* src2 = reinterpret_cast<const float2*>(in + (size_t)r * IN_HW);
    reinterpret_cast<float2*>(row)[t] = src2[t];
    __syncthreads();
    float sum = 0.0f;
    for (int j = 0; j < taps; ++j) {
        const int i = j * OUT_HW + t;
        sum = fmaf(__ldg(w + i), row[__ldg(fov + i)], sum);
    }
    out1[(size_t)r * OUT_HW + t] = sum;
}

__global__ void __launch_bounds__(256)
vpass_kernel(const float* __restrict__ s, const float* __restrict__ w,
             const int* __restrict__ fov, float4* __restrict__ out, int taps)
{
    const int idx = blockIdx.x * blockDim.x + threadIdx.x;
    const int ow4 = idx & 63;
    const int oh  = (idx >> 6) & (OUT_HW - 1);
    const int pl  = idx >> 14;
    const float4* base =
        reinterpret_cast<const float4*>(s + (size_t)pl * IN_HW * OUT_HW) + ow4;
    float4 acc = make_float4(0.f, 0.f, 0.f, 0.f);
    for (int j = 0; j < taps; ++j) {
        const int i = j * OUT_HW + oh;
        const float wj = __ldg(w + i);
        const float4 v = base[(size_t)__ldg(fov + i) * (OUT_HW / 4)];
        acc.x = fmaf(wj, v.x, acc.x);
        acc.y = fmaf(wj, v.y, acc.y);
        acc.z = fmaf(wj, v.z, acc.z);
        acc.w = fmaf(wj, v.w, acc.w);
    }
    out[idx] = acc;
}

// ===========================================================================
// Inputs (metadata order): in_tensor f32, w2 f32, fov2 i32, w3 f32, fov3 i32.
// ===========================================================================
extern "C" void kernel_launch(void* const* d_in, const int* in_sizes, int n_in,
                              void* d_out, int out_size)
{
    const float* in   = (const float*)d_in[0];
    const float* w2   = (const float*)d_in[1];
    const int*   fov2 = (const int*)  d_in[2];
    const float* w3   = (const float*)d_in[3];
    const int*   fov3 = (const int*)  d_in[4];

    const int taps = in_sizes[2] / OUT_HW;

    if (taps == TAPS) {
        const int smem_bytes = SMEM_FLOATS * (int)sizeof(float);   // 81920
        cudaFuncSetAttribute(fused_resize_kernel,
                             cudaFuncAttributeMaxDynamicSharedMemorySize, smem_bytes);
        fused_resize_kernel<<<N_PLANES * OH_BLKS, 256, smem_bytes>>>(
            in, w2, fov2, w3, fov3, (float*)d_out);
    } else {
        float* scratch = nullptr;
        cudaGetSymbolAddress((void**)&scratch, g_scratch);
        hpass_kernel<<<N_PLANES * IN_HW, OUT_HW>>>(in, w3, fov3, scratch, taps);
        const int n_vec4 = N_PLANES * OUT_HW * OUT_HW / 4;
        vpass_kernel<<<n_vec4 / 256, 256>>>(scratch, w2, fov2, (float4*)d_out, taps);
    }
}

// round 9
// speedup vs baseline: 1.3796x; 1.0062x over previous
#include <cuda_runtime.h>
#include <cstdint>

// Problem constants (IN_SHAPE = (32,3,512,512), OUT_HW = 256, scale 0.5)
#define N_PLANES   96          // N*C
#define IN_HW      512
#define OUT_HW     256
#define R_BLK      16          // output rows per CTA (fused path)
#define OH_BLKS    (OUT_HW / R_BLK)          // 16
#define MAX_ROWS   38          // exact max input-row span for R_BLK=16
#define TAPS       8
#define SMEM_FLOATS (MAX_ROWS * IN_HW)       // 19456 floats = 76 KB

// Scratch for the generic two-pass fallback only (~50 MB, static => legal).
__device__ float g_scratch[(size_t)N_PLANES * IN_HW * OUT_HW];

// ===========================================================================
// FUSED kernel (taps == 8). One CTA per (plane, 16-row output block).
// smem: MAX_ROWS rows of 512 floats, DEINTERLEAVED per row (even elems at
// [0,256), odd at [256,512)) -> stride-2 W gathers are conflict-free.
// W-pass: thread t owns column t; tables in registers; ALL row sums
// accumulate into a 38-entry register array with NO barriers (independent
// chains -> deep LDS pipelining). Then one barrier, in-place inter write,
// one barrier, vectorized H-pass. 3 barriers total vs ~40 in R6.
// ===========================================================================
__global__ void __launch_bounds__(256, 2)
fused_resize_kernel(const float* __restrict__ in,
                    const float* __restrict__ w2, const int* __restrict__ fov2,
                    const float* __restrict__ w3, const int* __restrict__ fov3,
                    float* __restrict__ out)
{
    extern __shared__ float smf[];
    __shared__ int s_rmin, s_rmax;

    const int t     = threadIdx.x;
    const int plane = blockIdx.x >> 4;                 // / OH_BLKS
    const int oh0   = (blockIdx.x & (OH_BLKS - 1)) * R_BLK;

    // ---- input-row span: min/max of fov2 over (8 taps x 16 oh) -------------
    {
        const int idx = t & 127;
        const int tap = idx >> 4, oo = idx & 15;
        int v = __ldg(fov2 + tap * OUT_HW + oh0 + oo);
        int vmin = v, vmax = v;
#pragma unroll
        for (int s = 16; s; s >>= 1) {
            vmin = min(vmin, __shfl_xor_sync(0xffffffffu, vmin, s));
            vmax = max(vmax, __shfl_xor_sync(0xffffffffu, vmax, s));
        }
        if (t == 0) { s_rmin = 1 << 30; s_rmax = -1; }
        __syncthreads();
        if ((t & 31) == 0) { atomicMin(&s_rmin, vmin); atomicMax(&s_rmax, vmax); }
        __syncthreads();
    }
    const int rmin  = s_rmin;
    const int nrows = min(s_rmax - rmin + 1, MAX_ROWS);

    // ---- per-thread W tables, loaded ONCE (ow = t) -------------------------
    float wreg[TAPS];
    int   preg[TAPS];           // deinterleaved smem position within a row
#pragma unroll
    for (int j = 0; j < TAPS; ++j) {
        wreg[j] = __ldg(w3 + j * OUT_HW + t);
        const int idx = __ldg(fov3 + j * OUT_HW + t);
        preg[j] = (idx >> 1) + ((idx & 1) << 8);
    }

    // ---- load nrows input rows, deinterleaving on the fly ------------------
    {
        const float4* pin = reinterpret_cast<const float4*>(
                                in + (size_t)plane * IN_HW * IN_HW)
                            + (size_t)rmin * (IN_HW / 4);
        float2* sm2 = reinterpret_cast<float2*>(smf);
        const int total = nrows * (IN_HW / 4);
        for (int i = t; i < total; i += 256) {
            const int row = i >> 7, c4 = i & 127;
            const float4 g = pin[(size_t)row * (IN_HW / 4) + c4];
            sm2[row * 256 + c4]       = make_float2(g.x, g.z);   // even phase
            sm2[row * 256 + 128 + c4] = make_float2(g.y, g.w);   // odd phase
        }
    }
    __syncthreads();

    // ---- W-pass: all rows into registers, ZERO barriers --------------------
    // Rows >= nrows read stale smem -> garbage sums stored to inter rows that
    // the H-pass never references (fov2 span == [rmin, rmin+nrows)). Safe.
    float acc[MAX_ROWS];
#pragma unroll
    for (int r = 0; r < MAX_ROWS; ++r) {
        const float* rb = smf + r * IN_HW;
        float s0 = 0.0f, s1 = 0.0f;
#pragma unroll
        for (int j = 0; j < TAPS; j += 2) {
            s0 = fmaf(wreg[j],     rb[preg[j]],     s0);
            s1 = fmaf(wreg[j + 1], rb[preg[j + 1]], s1);
        }
        acc[r] = s0 + s1;
    }
    __syncthreads();                       // all gathers done everywhere

    // in-place intermediate: inter[r] over row r's front 256 floats
#pragma unroll
    for (int r = 0; r < MAX_ROWS; ++r)
        smf[r * IN_HW + t] = acc[r];
    __syncthreads();

    // ---- H-pass: 16x256 outputs, float4-vectorized -------------------------
    const float4* iv = reinterpret_cast<const float4*>(smf);  // inter[r] @ r*128
    float4* ov = reinterpret_cast<float4*>(out + (size_t)plane * OUT_HW * OUT_HW);
#pragma unroll
    for (int q = 0; q < 4; ++q) {
        const int idx = q * 256 + t;
        const int ow4 = idx & 63;                   // lane-consecutive
        const int oh  = oh0 + (idx >> 6);           // warp-uniform
        float4 a0 = make_float4(0.f, 0.f, 0.f, 0.f);
        float4 a1 = make_float4(0.f, 0.f, 0.f, 0.f);
#pragma unroll
        for (int j = 0; j < TAPS; j += 2) {
            const int i0    = j * OUT_HW + oh;
            const int i1    = (j + 1) * OUT_HW + oh;
            const float w0  = __ldg(w2 + i0);
            const float w1  = __ldg(w2 + i1);
            const int   r0  = min(__ldg(fov2 + i0) - rmin, MAX_ROWS - 1);
            const int   r1  = min(__ldg(fov2 + i1) - rmin, MAX_ROWS - 1);
            const float4 x0 = iv[r0 * (IN_HW / 4) + ow4];
            const float4 x1 = iv[r1 * (IN_HW / 4) + ow4];
            a0.x = fmaf(w0, x0.x, a0.x); a0.y = fmaf(w0, x0.y, a0.y);
            a0.z = fmaf(w0, x0.z, a0.z); a0.w = fmaf(w0, x0.w, a0.w);
            a1.x = fmaf(w1, x1.x, a1.x); a1.y = fmaf(w1, x1.y, a1.y);
            a1.z = fmaf(w1, x1.z, a1.z); a1.w = fmaf(w1, x1.w, a1.w);
        }
        const float4 r4 = make_float4(a0.x + a1.x, a0.y + a1.y,
                                      a0.z + a1.z, a0.w + a1.w);
        ov[oh * (OUT_HW / 4) + ow4] = r4;
    }
}

// ===========================================================================
// Generic two-pass fallback (any taps).
// ===========================================================================
__global__ void __launch_bounds__(OUT_HW)
hpass_kernel(const float* __restrict__ in, const float* __restrict__ w,
             const int* __restrict__ fov, float* __restrict__ out1, int taps)
{
    __shared__ float row[IN_HW];
    const int r = blockIdx.x;
    const int t = threadIdx.x;
    const float2* src2 = reinterpret_cast<const float2*>(in + (size_t)r * IN_HW);
    reinterpret_cast<float2*>(row)[t] = src2[t];
    __syncthreads();
    float sum = 0.0f;
    for (int j = 0; j < taps; ++j) {
        const int i = j * OUT_HW + t;
        sum = fmaf(__ldg(w + i), row[__ldg(fov + i)], sum);
    }
    out1[(size_t)r * OUT_HW + t] = sum;
}

__global__ void __launch_bounds__(256)
vpass_kernel(const float* __restrict__ s, const float* __restrict__ w,
             const int* __restrict__ fov, float4* __restrict__ out, int taps)
{
    const int idx = blockIdx.x * blockDim.x + threadIdx.x;
    const int ow4 = idx & 63;
    const int oh  = (idx >> 6) & (OUT_HW - 1);
    const int pl  = idx >> 14;
    const float4* base =
        reinterpret_cast<const float4*>(s + (size_t)pl * IN_HW * OUT_HW) + ow4;
    float4 acc = make_float4(0.f, 0.f, 0.f, 0.f);
    for (int j = 0; j < taps; ++j) {
        const int i = j * OUT_HW + oh;
        const float wj = __ldg(w + i);
        const float4 v = base[(size_t)__ldg(fov + i) * (OUT_HW / 4)];
        acc.x = fmaf(wj, v.x, acc.x);
        acc.y = fmaf(wj, v.y, acc.y);
        acc.z = fmaf(wj, v.z, acc.z);
        acc.w = fmaf(wj, v.w, acc.w);
    }
    out[idx] = acc;
}

// ===========================================================================
// Inputs (metadata order): in_tensor f32, w2 f32, fov2 i32, w3 f32, fov3 i32.
// ===========================================================================
extern "C" void kernel_launch(void* const* d_in, const int* in_sizes, int n_in,
                              void* d_out, int out_size)
{
    const float* in   = (const float*)d_in[0];
    const float* w2   = (const float*)d_in[1];
    const int*   fov2 = (const int*)  d_in[2];
    const float* w3   = (const float*)d_in[3];
    const int*   fov3 = (const int*)  d_in[4];

    const int taps = in_sizes[2] / OUT_HW;

    if (taps == TAPS) {
        const int smem_bytes = SMEM_FLOATS * (int)sizeof(float);   // 77824
        cudaFuncSetAttribute(fused_resize_kernel,
                             cudaFuncAttributeMaxDynamicSharedMemorySize, smem_bytes);
        fused_resize_kernel<<<N_PLANES * OH_BLKS, 256, smem_bytes>>>(
            in, w2, fov2, w3, fov3, (float*)d_out);
    } else {
        float* scratch = nullptr;
        cudaGetSymbolAddress((void**)&scratch, g_scratch);
        hpass_kernel<<<N_PLANES * IN_HW, OUT_HW>>>(in, w3, fov3, scratch, taps);
        const int n_vec4 = N_PLANES * OUT_HW * OUT_HW / 4;
        vpass_kernel<<<n_vec4 / 256, 256>>>(scratch, w2, fov2, (float4*)d_out, taps);
    }
}

// round 10
// speedup vs baseline: 1.5308x; 1.1096x over previous
#include <cuda_runtime.h>
#include <cstdint>

// Problem constants (IN_SHAPE = (32,3,512,512), OUT_HW = 256, scale 0.5)
#define N_PLANES   96          // N*C
#define IN_HW      512
#define OUT_HW     256
#define R_BLK      8           // output rows per CTA (fused path)
#define OH_BLKS    (OUT_HW / R_BLK)          // 32
#define MAX_ROWS   22          // exact max input-row span for R_BLK=8 (2*7+8)
#define RCHUNK     11          // W-pass register-accumulator chunk
#define TAPS       8
#define SMEM_FLOATS (MAX_ROWS * IN_HW)       // 11264 floats = 44 KB

// Scratch for the generic two-pass fallback only (~50 MB, static => legal).
__device__ float g_scratch[(size_t)N_PLANES * IN_HW * OUT_HW];

// ===========================================================================
// FUSED kernel (taps == 8). One CTA per (plane, 8-row output block).
// smem: MAX_ROWS rows of 512 floats, DEINTERLEAVED per row (even elems at
// [0,256), odd at [256,512)) -> stride-2 W gathers are conflict-free.
// W-pass: thread t owns column t; tables in registers; rows processed in 2
// chunks of 11 register accumulators (keeps regs <= 64 -> 4 CTAs/SM).
// Chunk k gathers rows [11k, 11k+11); inter writes only touch row FRONTS of
// already-finished rows, so chunk 2's gathers (rows 11..21) never race them.
// ===========================================================================
__global__ void __launch_bounds__(256, 4)
fused_resize_kernel(const float* __restrict__ in,
                    const float* __restrict__ w2, const int* __restrict__ fov2,
                    const float* __restrict__ w3, const int* __restrict__ fov3,
                    float* __restrict__ out)
{
    extern __shared__ float smf[];
    __shared__ int s_rmin, s_rmax;

    const int t     = threadIdx.x;
    const int plane = blockIdx.x >> 5;                 // / OH_BLKS
    const int oh0   = (blockIdx.x & (OH_BLKS - 1)) * R_BLK;

    // ---- input-row span: min/max of fov2 over (8 taps x 8 oh) --------------
    {
        const int idx = t & 63;
        const int tap = idx >> 3, oo = idx & 7;
        int v = __ldg(fov2 + tap * OUT_HW + oh0 + oo);
        int vmin = v, vmax = v;
#pragma unroll
        for (int s = 16; s; s >>= 1) {
            vmin = min(vmin, __shfl_xor_sync(0xffffffffu, vmin, s));
            vmax = max(vmax, __shfl_xor_sync(0xffffffffu, vmax, s));
        }
        if (t == 0) { s_rmin = 1 << 30; s_rmax = -1; }
        __syncthreads();
        if ((t & 31) == 0) { atomicMin(&s_rmin, vmin); atomicMax(&s_rmax, vmax); }
        __syncthreads();
    }
    const int rmin  = s_rmin;
    const int nrows = min(s_rmax - rmin + 1, MAX_ROWS);

    // ---- per-thread W tables, loaded ONCE (ow = t) -------------------------
    float wreg[TAPS];
    int   preg[TAPS];           // deinterleaved smem position within a row
#pragma unroll
    for (int j = 0; j < TAPS; ++j) {
        wreg[j] = __ldg(w3 + j * OUT_HW + t);
        const int idx = __ldg(fov3 + j * OUT_HW + t);
        preg[j] = (idx >> 1) + ((idx & 1) << 8);
    }

    // ---- load nrows input rows, deinterleaving on the fly ------------------
    {
        const float4* pin = reinterpret_cast<const float4*>(
                                in + (size_t)plane * IN_HW * IN_HW)
                            + (size_t)rmin * (IN_HW / 4);
        float2* sm2 = reinterpret_cast<float2*>(smf);
        const int total = nrows * (IN_HW / 4);
        for (int i = t; i < total; i += 256) {
            const int row = i >> 7, c4 = i & 127;
            const float4 g = pin[(size_t)row * (IN_HW / 4) + c4];
            sm2[row * 256 + c4]       = make_float2(g.x, g.z);   // even phase
            sm2[row * 256 + 128 + c4] = make_float2(g.y, g.w);   // odd phase
        }
    }
    __syncthreads();

    // ---- W-pass: 2 chunks of 11 rows, register accumulators ---------------
    // Rows >= nrows produce garbage sums into inter rows the H-pass never
    // references (fov2 span == [rmin, rmin+nrows)). Safe.
#pragma unroll
    for (int c = 0; c < 2; ++c) {
        const int rbase = c * RCHUNK;
        float acc[RCHUNK];
#pragma unroll
        for (int r = 0; r < RCHUNK; ++r) {
            const float* rb = smf + (rbase + r) * IN_HW;
            float s0 = 0.0f, s1 = 0.0f;
#pragma unroll
            for (int j = 0; j < TAPS; j += 2) {
                s0 = fmaf(wreg[j],     rb[preg[j]],     s0);
                s1 = fmaf(wreg[j + 1], rb[preg[j + 1]], s1);
            }
            acc[r] = s0 + s1;
        }
        __syncthreads();                   // chunk's gathers done CTA-wide
#pragma unroll
        for (int r = 0; r < RCHUNK; ++r)   // in-place: row fronts of this chunk
            smf[(rbase + r) * IN_HW + t] = acc[r];
        // no barrier needed before next chunk: chunk 2 gathers rows 11..21,
        // untouched by these writes (rows 0..10 fronts).
    }
    __syncthreads();

    // ---- H-pass: 8x256 outputs, float4-vectorized --------------------------
    const float4* iv = reinterpret_cast<const float4*>(smf);  // inter[r] @ r*128
    float4* ov = reinterpret_cast<float4*>(out + (size_t)plane * OUT_HW * OUT_HW);
#pragma unroll
    for (int q = 0; q < 2; ++q) {
        const int idx = q * 256 + t;
        const int ow4 = idx & 63;                   // lane-consecutive
        const int oh  = oh0 + (idx >> 6);           // warp-uniform
        float4 a0 = make_float4(0.f, 0.f, 0.f, 0.f);
        float4 a1 = make_float4(0.f, 0.f, 0.f, 0.f);
#pragma unroll
        for (int j = 0; j < TAPS; j += 2) {
            const int i0    = j * OUT_HW + oh;
            const int i1    = (j + 1) * OUT_HW + oh;
            const float w0  = __ldg(w2 + i0);
            const float w1  = __ldg(w2 + i1);
            const int   r0  = min(__ldg(fov2 + i0) - rmin, MAX_ROWS - 1);
            const int   r1  = min(__ldg(fov2 + i1) - rmin, MAX_ROWS - 1);
            const float4 x0 = iv[r0 * (IN_HW / 4) + ow4];
            const float4 x1 = iv[r1 * (IN_HW / 4) + ow4];
            a0.x = fmaf(w0, x0.x, a0.x); a0.y = fmaf(w0, x0.y, a0.y);
            a0.z = fmaf(w0, x0.z, a0.z); a0.w = fmaf(w0, x0.w, a0.w);
            a1.x = fmaf(w1, x1.x, a1.x); a1.y = fmaf(w1, x1.y, a1.y);
            a1.z = fmaf(w1, x1.z, a1.z); a1.w = fmaf(w1, x1.w, a1.w);
        }
        const float4 r4 = make_float4(a0.x + a1.x, a0.y + a1.y,
                                      a0.z + a1.z, a0.w + a1.w);
        ov[oh * (OUT_HW / 4) + ow4] = r4;
    }
}

// ===========================================================================
// Generic two-pass fallback (any taps).
// ===========================================================================
__global__ void __launch_bounds__(OUT_HW)
hpass_kernel(const float* __restrict__ in, const float* __restrict__ w,
             const int* __restrict__ fov, float* __restrict__ out1, int taps)
{
    __shared__ float row[IN_HW];
    const int r = blockIdx.x;
    const int t = threadIdx.x;
    const float2* src2 = reinterpret_cast<const float2*>(in + (size_t)r * IN_HW);
    reinterpret_cast<float2*>(row)[t] = src2[t];
    __syncthreads();
    float sum = 0.0f;
    for (int j = 0; j < taps; ++j) {
        const int i = j * OUT_HW + t;
        sum = fmaf(__ldg(w + i), row[__ldg(fov + i)], sum);
    }
    out1[(size_t)r * OUT_HW + t] = sum;
}

__global__ void __launch_bounds__(256)
vpass_kernel(const float* __restrict__ s, const float* __restrict__ w,
             const int* __restrict__ fov, float4* __restrict__ out, int taps)
{
    const int idx = blockIdx.x * blockDim.x + threadIdx.x;
    const int ow4 = idx & 63;
    const int oh  = (idx >> 6) & (OUT_HW - 1);
    const int pl  = idx >> 14;
    const float4* base =
        reinterpret_cast<const float4*>(s + (size_t)pl * IN_HW * OUT_HW) + ow4;
    float4 acc = make_float4(0.f, 0.f, 0.f, 0.f);
    for (int j = 0; j < taps; ++j) {
        const int i = j * OUT_HW + oh;
        const float wj = __ldg(w + i);
        const float4 v = base[(size_t)__ldg(fov + i) * (OUT_HW / 4)];
        acc.x = fmaf(wj, v.x, acc.x);
        acc.y = fmaf(wj, v.y, acc.y);
        acc.z = fmaf(wj, v.z, acc.z);
        acc.w = fmaf(wj, v.w, acc.w);
    }
    out[idx] = acc;
}

// ===========================================================================
// Inputs (metadata order): in_tensor f32, w2 f32, fov2 i32, w3 f32, fov3 i32.
// ===========================================================================
extern "C" void kernel_launch(void* const* d_in, const int* in_sizes, int n_in,
                              void* d_out, int out_size)
{
    const float* in   = (const float*)d_in[0];
    const float* w2   = (const float*)d_in[1];
    const int*   fov2 = (const int*)  d_in[2];
    const float* w3   = (const float*)d_in[3];
    const int*   fov3 = (const int*)  d_in[4];

    const int taps = in_sizes[2] / OUT_HW;

    if (taps == TAPS) {
        const int smem_bytes = SMEM_FLOATS * (int)sizeof(float);   // 45056
        fused_resize_kernel<<<N_PLANES * OH_BLKS, 256, smem_bytes>>>(
            in, w2, fov2, w3, fov3, (float*)d_out);
    } else {
        float* scratch = nullptr;
        cudaGetSymbolAddress((void**)&scratch, g_scratch);
        hpass_kernel<<<N_PLANES * IN_HW, OUT_HW>>>(in, w3, fov3, scratch, taps);
        const int n_vec4 = N_PLANES * OUT_HW * OUT_HW / 4;
        vpass_kernel<<<n_vec4 / 256, 256>>>(scratch, w2, fov2, (float4*)d_out, taps);
    }
}

// round 13
// speedup vs baseline: 2.3609x; 1.5423x over previous
#include <cuda_runtime.h>
#include <cstdint>

// Problem constants (IN_SHAPE = (32,3,512,512), OUT_HW = 256, scale 0.5)
#define N_PLANES   96          // N*C
#define IN_HW      512
#define OUT_HW     256
#define R_BLK      8           // output rows per CTA
#define OH_BLKS    (OUT_HW / R_BLK)          // 32
#define TAPS       8

// Scratch for the generic two-pass fallback only (~50 MB, static => legal).
__device__ float g_scratch[(size_t)N_PLANES * IN_HW * OUT_HW];

// ===========================================================================
// FUSED kernel, V-FIRST (taps == 8). One CTA per (plane, 8-output-row block).
//
// V-pass: warp w owns output row oh = oh0 + (t>>5). Row indices fov2[j][oh]
// are warp-uniform -> NO gathers: 8 coalesced LDG.128 per float4 column chunk,
// FMA, write intermediate row to smem DEINTERLEAVED (even cols [0,256),
// odd [256,512)). Input rows come straight from global (L1 caches the ~44KB
// row window; no staging, no row-span computation).
//
// W-pass: thread t owns output column ow = t; tables in registers; gathers on
// only 8 intermediate rows, conflict-free thanks to the deinterleave
// (stride-2 input index -> stride-1 smem position per tap parity).
// ===========================================================================
__global__ void __launch_bounds__(256, 5)
fused_resize_kernel(const float* __restrict__ in,
                    const float* __restrict__ w2, const int* __restrict__ fov2,
                    const float* __restrict__ w3, const int* __restrict__ fov3,
                    float* __restrict__ out)
{
    __shared__ float inter[R_BLK * IN_HW];     // 8 x 512 floats = 16 KB

    const int t     = threadIdx.x;
    const int plane = blockIdx.x >> 5;                 // / OH_BLKS
    const int oh0   = (blockIdx.x & (OH_BLKS - 1)) * R_BLK;

    // ---- V-pass --------------------------------------------------------
    {
        const int ohl  = t >> 5;                       // warp -> output row
        const int lane = t & 31;
        const int oh   = oh0 + ohl;
        const char* pin = reinterpret_cast<const char*>(
                              in + (size_t)plane * IN_HW * IN_HW);

        float    wv[TAPS];
        unsigned off[TAPS];                            // byte offset of row
#pragma unroll
        for (int j = 0; j < TAPS; ++j) {
            wv[j]  = __ldg(w2 + j * OUT_HW + oh);
            off[j] = (unsigned)__ldg(fov2 + j * OUT_HW + oh) * (IN_HW * 4u);
        }

        float* ev = inter + ohl * IN_HW;               // even phase
        float* od = ev + 256;                          // odd phase
#pragma unroll
        for (int q = 0; q < 4; ++q) {
            const int c4 = lane + 32 * q;              // float4 column chunk
            const char* pc = pin + (size_t)c4 * 16;
            float4 a = make_float4(0.f, 0.f, 0.f, 0.f);
#pragma unroll
            for (int j = 0; j < TAPS; ++j) {
                const float4 v =
                    __ldg(reinterpret_cast<const float4*>(pc + off[j]));
                a.x = fmaf(wv[j], v.x, a.x);
                a.y = fmaf(wv[j], v.y, a.y);
                a.z = fmaf(wv[j], v.z, a.z);
                a.w = fmaf(wv[j], v.w, a.w);
            }
            // elements 4c4..4c4+3 -> even {2c4,2c4+1}, odd {2c4,2c4+1}
            reinterpret_cast<float2*>(ev)[c4] = make_float2(a.x, a.z);
            reinterpret_cast<float2*>(od)[c4] = make_float2(a.y, a.w);
        }
    }
    __syncthreads();

    // ---- W-pass: thread t owns output column ow = t ---------------------
    {
        float wr[TAPS];
        int   pr[TAPS];                                // deinterleaved position
#pragma unroll
        for (int j = 0; j < TAPS; ++j) {
            wr[j] = __ldg(w3 + j * OUT_HW + t);
            const int idx = __ldg(fov3 + j * OUT_HW + t);
            pr[j] = (idx >> 1) + ((idx & 1) << 8);
        }
        float* op = out + (size_t)plane * OUT_HW * OUT_HW
                        + (size_t)oh0 * OUT_HW + t;
#pragma unroll
        for (int r = 0; r < R_BLK; ++r) {
            const float* rb = inter + r * IN_HW;
            float s0 = 0.f, s1 = 0.f;
#pragma unroll
            for (int j = 0; j < TAPS; j += 2) {
                s0 = fmaf(wr[j],     rb[pr[j]],     s0);
                s1 = fmaf(wr[j + 1], rb[pr[j + 1]], s1);
            }
            op[r * OUT_HW] = s0 + s1;                  // coalesced per warp
        }
    }
}

// ===========================================================================
// Generic two-pass fallback (any taps).
// ===========================================================================
__global__ void __launch_bounds__(OUT_HW)
hpass_kernel(const float* __restrict__ in, const float* __restrict__ w,
             const int* __restrict__ fov, float* __restrict__ out1, int taps)
{
    __shared__ float row[IN_HW];
    const int r = blockIdx.x;
    const int t = threadIdx.x;
    const float2* src2 = reinterpret_cast<const float2*>(in + (size_t)r * IN_HW);
    reinterpret_cast<float2*>(row)[t] = src2[t];
    __syncthreads();
    float sum = 0.0f;
    for (int j = 0; j < taps; ++j) {
        const int i = j * OUT_HW + t;
        sum = fmaf(__ldg(w + i), row[__ldg(fov + i)], sum);
    }
    out1[(size_t)r * OUT_HW + t] = sum;
}

__global__ void __launch_bounds__(256)
vpass_kernel(const float* __restrict__ s, const float* __restrict__ w,
             const int* __restrict__ fov, float4* __restrict__ out, int taps)
{
    const int idx = blockIdx.x * blockDim.x + threadIdx.x;
    const int ow4 = idx & 63;
    const int oh  = (idx >> 6) & (OUT_HW - 1);
    const int pl  = idx >> 14;
    const float4* base =
        reinterpret_cast<const float4*>(s + (size_t)pl * IN_HW * OUT_HW) + ow4;
    float4 acc = make_float4(0.f, 0.f, 0.f, 0.f);
    for (int j = 0; j < taps; ++j) {
        const int i = j * OUT_HW + oh;
        const float wj = __ldg(w + i);
        const float4 v = base[(size_t)__ldg(fov + i) * (OUT_HW / 4)];
        acc.x = fmaf(wj, v.x, acc.x);
        acc.y = fmaf(wj, v.y, acc.y);
        acc.z = fmaf(wj, v.z, acc.z);
        acc.w = fmaf(wj, v.w, acc.w);
    }
    out[idx] = acc;
}

// ===========================================================================
// Inputs (metadata order): in_tensor f32, w2 f32, fov2 i32, w3 f32, fov3 i32.
// ===========================================================================
extern "C" void kernel_launch(void* const* d_in, const int* in_sizes, int n_in,
                              void* d_out, int out_size)
{
    const float* in   = (const float*)d_in[0];
    const float* w2   = (const float*)d_in[1];
    const int*   fov2 = (const int*)  d_in[2];
    const float* w3   = (const float*)d_in[3];
    const int*   fov3 = (const int*)  d_in[4];

    const int taps = in_sizes[2] / OUT_HW;

    if (taps == TAPS) {
        fused_resize_kernel<<<N_PLANES * OH_BLKS, 256>>>(
            in, w2, fov2, w3, fov3, (float*)d_out);
    } else {
        float* scratch = nullptr;
        cudaGetSymbolAddress((void**)&scratch, g_scratch);
        hpass_kernel<<<N_PLANES * IN_HW, OUT_HW>>>(in, w3, fov3, scratch, taps);
        const int n_vec4 = N_PLANES * OUT_HW * OUT_HW / 4;
        vpass_kernel<<<n_vec4 / 256, 256>>>(scratch, w2, fov2, (float4*)d_out, taps);
    }
}

// round 14
// speedup vs baseline: 2.5813x; 1.0934x over previous
#include <cuda_runtime.h>
#include <cstdint>

// Problem constants (IN_SHAPE = (32,3,512,512), OUT_HW = 256, scale 0.5)
#define N_PLANES   96          // N*C
#define IN_HW      512
#define OUT_HW     256
#define R_BLK      8           // output rows per CTA
#define OH_BLKS    (OUT_HW / R_BLK)          // 32
#define TAPS       8
#define FULLM      0xffffffffu

// Scratch for the generic two-pass fallback only (~50 MB, static => legal).
__device__ float g_scratch[(size_t)N_PLANES * IN_HW * OUT_HW];

// ===========================================================================
// FUSED kernel, V-FIRST + sliding window (taps == 8).
// One CTA per (plane, 8-output-row block).
//
// V-pass: warp = (column chunk q = wid&3, oh run half = wid>>2). Each warp
// walks 4 SEQUENTIAL output rows keeping the 8 tap input-rows in a float4
// register window. The stride-2 tap window means consecutive oh usually share
// 6 rows: detected at runtime (lanes 0..7 hold this step's fov2 entries;
// __all_sync compares them against the previous step's, shifted by 2). On
// match: shift window, load 2 new rows. Else: full 8-row reload (edges).
// Weights/row-offsets broadcast from lanes 0..7 via __shfl_sync.
// Intermediate rows written to smem DEINTERLEAVED (even cols [0,256), odd
// [256,512)) -> W-pass stride-2 gathers are conflict-free.
//
// W-pass: thread t owns output column t; tables in registers; gathers on 8
// intermediate rows only.
// ===========================================================================
__global__ void __launch_bounds__(256, 4)
fused_resize_kernel(const float* __restrict__ in,
                    const float* __restrict__ w2, const int* __restrict__ fov2,
                    const float* __restrict__ w3, const int* __restrict__ fov3,
                    float* __restrict__ out)
{
    __shared__ float inter[R_BLK * IN_HW];     // 8 x 512 floats = 16 KB

    const int t     = threadIdx.x;
    const int lane  = t & 31;
    const int wid   = t >> 5;
    const int plane = blockIdx.x >> 5;                 // / OH_BLKS
    const int oh0   = (blockIdx.x & (OH_BLKS - 1)) * R_BLK;

    // ---- V-pass: sliding register window over 4 sequential output rows ----
    {
        const int q    = wid & 3;                      // column chunk
        const int half = wid >> 2;                     // which 4-oh run
        const int c4   = lane + 32 * q;                // float4 column
        const char* pc = reinterpret_cast<const char*>(
                             in + (size_t)plane * IN_HW * IN_HW)
                         + (size_t)c4 * 16;

        float4 v[TAPS];
        int f = 0;                                     // lane<8: prev fov2 entry

#pragma unroll
        for (int s = 0; s < 4; ++s) {
            const int ohl = half * 4 + s;
            const int oh  = oh0 + ohl;

            // lanes 0..7 fetch this oh's table entries
            int nf = 0; float nw = 0.0f;
            if (lane < TAPS) {
                nf = __ldg(fov2 + lane * OUT_HW + oh);
                nw = __ldg(w2   + lane * OUT_HW + oh);
            }

            // window-shift test: nf[j] == f[j+2] for j = 0..5 (warp-uniform)
            bool ok = false;
            if (s > 0) {
                const int fj2 = __shfl_sync(FULLM, f, (lane + 2) & 31);
                ok = __all_sync(FULLM, (lane >= 6) | (nf == fj2));
            }

            if (ok) {
#pragma unroll
                for (int j = 0; j < 6; ++j) v[j] = v[j + 2];
                const unsigned o6 = (unsigned)__shfl_sync(FULLM, nf, 6) * (IN_HW * 4u);
                const unsigned o7 = (unsigned)__shfl_sync(FULLM, nf, 7) * (IN_HW * 4u);
                v[6] = __ldg(reinterpret_cast<const float4*>(pc + o6));
                v[7] = __ldg(reinterpret_cast<const float4*>(pc + o7));
            } else {
#pragma unroll
                for (int j = 0; j < TAPS; ++j) {
                    const unsigned oj =
                        (unsigned)__shfl_sync(FULLM, nf, j) * (IN_HW * 4u);
                    v[j] = __ldg(reinterpret_cast<const float4*>(pc + oj));
                }
            }
            f = nf;

            float4 a = make_float4(0.f, 0.f, 0.f, 0.f);
#pragma unroll
            for (int j = 0; j < TAPS; ++j) {
                const float wj = __shfl_sync(FULLM, nw, j);
                a.x = fmaf(wj, v[j].x, a.x);
                a.y = fmaf(wj, v[j].y, a.y);
                a.z = fmaf(wj, v[j].z, a.z);
                a.w = fmaf(wj, v[j].w, a.w);
            }

            // deinterleaved store: elems 4c4..4c4+3 -> even/odd phase pairs
            float* ev = inter + ohl * IN_HW;
            reinterpret_cast<float2*>(ev)[c4]       = make_float2(a.x, a.z);
            reinterpret_cast<float2*>(ev + 256)[c4] = make_float2(a.y, a.w);
        }
    }
    __syncthreads();

    // ---- W-pass: thread t owns output column ow = t ---------------------
    {
        float wr[TAPS];
        int   pr[TAPS];                                // deinterleaved position
#pragma unroll
        for (int j = 0; j < TAPS; ++j) {
            wr[j] = __ldg(w3 + j * OUT_HW + t);
            const int idx = __ldg(fov3 + j * OUT_HW + t);
            pr[j] = (idx >> 1) + ((idx & 1) << 8);
        }
        float* op = out + (size_t)plane * OUT_HW * OUT_HW
                        + (size_t)oh0 * OUT_HW + t;
#pragma unroll
        for (int r = 0; r < R_BLK; ++r) {
            const float* rb = inter + r * IN_HW;
            float s0 = 0.f, s1 = 0.f;
#pragma unroll
            for (int j = 0; j < TAPS; j += 2) {
                s0 = fmaf(wr[j],     rb[pr[j]],     s0);
                s1 = fmaf(wr[j + 1], rb[pr[j + 1]], s1);
            }
            op[r * OUT_HW] = s0 + s1;                  // coalesced per warp
        }
    }
}

// ===========================================================================
// Generic two-pass fallback (any taps).
// ===========================================================================
__global__ void __launch_bounds__(OUT_HW)
hpass_kernel(const float* __restrict__ in, const float* __restrict__ w,
             const int* __restrict__ fov, float* __restrict__ out1, int taps)
{
    __shared__ float row[IN_HW];
    const int r = blockIdx.x;
    const int t = threadIdx.x;
    const float2* src2 = reinterpret_cast<const float2*>(in + (size_t)r * IN_HW);
    reinterpret_cast<float2*>(row)[t] = src2[t];
    __syncthreads();
    float sum = 0.0f;
    for (int j = 0; j < taps; ++j) {
        const int i = j * OUT_HW + t;
        sum = fmaf(__ldg(w + i), row[__ldg(fov + i)], sum);
    }
    out1[(size_t)r * OUT_HW + t] = sum;
}

__global__ void __launch_bounds__(256)
vpass_kernel(const float* __restrict__ s, const float* __restrict__ w,
             const int* __restrict__ fov, float4* __restrict__ out, int taps)
{
    const int idx = blockIdx.x * blockDim.x + threadIdx.x;
    const int ow4 = idx & 63;
    const int oh  = (idx >> 6) & (OUT_HW - 1);
    const int pl  = idx >> 14;
    const float4* base =
        reinterpret_cast<const float4*>(s + (size_t)pl * IN_HW * OUT_HW) + ow4;
    float4 acc = make_float4(0.f, 0.f, 0.f, 0.f);
    for (int j = 0; j < taps; ++j) {
        const int i = j * OUT_HW + oh;
        const float wj = __ldg(w + i);
        const float4 v = base[(size_t)__ldg(fov + i) * (OUT_HW / 4)];
        acc.x = fmaf(wj, v.x, acc.x);
        acc.y = fmaf(wj, v.y, acc.y);
        acc.z = fmaf(wj, v.z, acc.z);
        acc.w = fmaf(wj, v.w, acc.w);
    }
    out[idx] = acc;
}

// ===========================================================================
// Inputs (metadata order): in_tensor f32, w2 f32, fov2 i32, w3 f32, fov3 i32.
// ===========================================================================
extern "C" void kernel_launch(void* const* d_in, const int* in_sizes, int n_in,
                              void* d_out, int out_size)
{
    const float* in   = (const float*)d_in[0];
    const float* w2   = (const float*)d_in[1];
    const int*   fov2 = (const int*)  d_in[2];
    const float* w3   = (const float*)d_in[3];
    const int*   fov3 = (const int*)  d_in[4];

    const int taps = in_sizes[2] / OUT_HW;

    if (taps == TAPS) {
        fused_resize_kernel<<<N_PLANES * OH_BLKS, 256>>>(
            in, w2, fov2, w3, fov3, (float*)d_out);
    } else {
        float* scratch = nullptr;
        cudaGetSymbolAddress((void**)&scratch, g_scratch);
        hpass_kernel<<<N_PLANES * IN_HW, OUT_HW>>>(in, w3, fov3, scratch, taps);
        const int n_vec4 = N_PLANES * OUT_HW * OUT_HW / 4;
        vpass_kernel<<<n_vec4 / 256, 256>>>(scratch, w2, fov2, (float4*)d_out, taps);
    }
}